// round 14
// baseline (speedup 1.0000x reference)
#include <cuda_runtime.h>
#include <cuda_fp16.h>
#include <math.h>
#include <stdint.h>

#define D_MODEL 1024
#define S_LEN   2048
#define BATCH   2
#define NHEADS  16
#define HDIM    64
#define M_TOT   (BATCH * S_LEN)   // 4096

// Scratch (no cudaMalloc allowed)
__device__ __half g_xh [(size_t)M_TOT * D_MODEL];
__device__ __half g_xl [(size_t)M_TOT * D_MODEL];
__device__ __half g_Wqh[(size_t)D_MODEL * D_MODEL];
__device__ __half g_Woh[(size_t)D_MODEL * D_MODEL];
__device__ __half g_Wkh[(size_t)D_MODEL * HDIM];
__device__ __half g_Wkl[(size_t)D_MODEL * HDIM];
__device__ __half g_Wvh[(size_t)D_MODEL * HDIM];
__device__ __half g_Wvl[(size_t)D_MODEL * HDIM];
__device__ __half g_Qh [(size_t)M_TOT * D_MODEL];
__device__ __half g_Kh [(size_t)M_TOT * HDIM];
__device__ __half g_Vh [(size_t)M_TOT * HDIM];
__device__ __half g_ah [(size_t)M_TOT * D_MODEL];

// ---------------------------------------------------------------------------
// helpers
// ---------------------------------------------------------------------------
__device__ __forceinline__ uint32_t s2u(const void* p) {
    return (uint32_t)__cvta_generic_to_shared(p);
}
__device__ __forceinline__ void cp16(void* s, const void* g) {
    asm volatile("cp.async.cg.shared.global [%0],[%1],16;\n" :: "r"(s2u(s)), "l"(g));
}
__device__ __forceinline__ void cp_commit() {
    asm volatile("cp.async.commit_group;\n");
}
template<int N> __device__ __forceinline__ void cp_wait() {
    asm volatile("cp.async.wait_group %0;\n" :: "n"(N));
}
__device__ __forceinline__ void ldsm4(uint32_t& r0, uint32_t& r1, uint32_t& r2, uint32_t& r3,
                                      const __half* p) {
    asm volatile("ldmatrix.sync.aligned.m8n8.x4.shared.b16 {%0,%1,%2,%3},[%4];"
                 : "=r"(r0), "=r"(r1), "=r"(r2), "=r"(r3) : "r"(s2u(p)));
}
__device__ __forceinline__ void ldsm4t(uint32_t& r0, uint32_t& r1, uint32_t& r2, uint32_t& r3,
                                       const __half* p) {
    asm volatile("ldmatrix.sync.aligned.m8n8.x4.trans.shared.b16 {%0,%1,%2,%3},[%4];"
                 : "=r"(r0), "=r"(r1), "=r"(r2), "=r"(r3) : "r"(s2u(p)));
}
__device__ __forceinline__ void mma16816(float c[4],
    uint32_t a0, uint32_t a1, uint32_t a2, uint32_t a3, uint32_t b0, uint32_t b1) {
    asm volatile(
        "mma.sync.aligned.m16n8k16.row.col.f32.f16.f16.f32 "
        "{%0,%1,%2,%3},{%4,%5,%6,%7},{%8,%9},{%0,%1,%2,%3};"
        : "+f"(c[0]), "+f"(c[1]), "+f"(c[2]), "+f"(c[3])
        : "r"(a0), "r"(a1), "r"(a2), "r"(a3), "r"(b0), "r"(b1));
}
__device__ __forceinline__ uint32_t packh2(float lo, float hi) {
    __half2 h = __floats2half2_rn(lo, hi);
    return *(uint32_t*)&h;
}
__device__ __forceinline__ float ex2(float x) {
    float y; asm("ex2.approx.f32 %0,%1;" : "=f"(y) : "f"(x)); return y;
}

// ---------------------------------------------------------------------------
// Fused fp32 -> fp16 convert for ALL operands in ONE launch (bit-identical)
// ---------------------------------------------------------------------------
__global__ __launch_bounds__(256) void conv_all(
    const float* __restrict__ x,  __half* __restrict__ xh,  __half* __restrict__ xl,
    const float* __restrict__ Wq, __half* __restrict__ Wqh,
    const float* __restrict__ Wo, __half* __restrict__ Woh,
    const float* __restrict__ Wk, __half* __restrict__ Wkh, __half* __restrict__ Wkl,
    const float* __restrict__ Wv, __half* __restrict__ Wvh, __half* __restrict__ Wvl)
{
    int b = blockIdx.x;
    const float* src; __half* dh; __half* dl;
    if (b < 2048)      { src = x;  dh = xh;  dl = xl;  }
    else if (b < 2560) { src = Wq; dh = Wqh; dl = 0; b -= 2048; }
    else if (b < 3072) { src = Wo; dh = Woh; dl = 0; b -= 2560; }
    else if (b < 3104) { src = Wk; dh = Wkh; dl = Wkl; b -= 3072; }
    else               { src = Wv; dh = Wvh; dl = Wvl; b -= 3104; }

    int i = (b * 256 + threadIdx.x) * 8;
    float v[8];
    *(float4*)(v)     = *(const float4*)(src + i);
    *(float4*)(v + 4) = *(const float4*)(src + i + 4);
    __half h[8];
    #pragma unroll
    for (int j = 0; j < 8; j++) h[j] = __float2half_rn(v[j]);
    *(uint4*)(dh + i) = *(uint4*)h;
    if (dl) {
        __half l[8];
        #pragma unroll
        for (int j = 0; j < 8; j++)
            l[j] = __float2half_rn(v[j] - __half2float(h[j]));
        *(uint4*)(dl + i) = *(uint4*)l;
    }
}

// ---------------------------------------------------------------------------
// fp16 tensor GEMM + bias (unchanged from R12, unconditional commits)
// ---------------------------------------------------------------------------
template<bool OUT_HALF>
__global__ __launch_bounds__(256) void gemm_h(
    const __half* __restrict__ A, const __half* __restrict__ W,
    const float* __restrict__ bias, void* __restrict__ Cv,
    int M, int N, int K)
{
    __shared__ __half As[3][128 * 40];
    __shared__ __half Ws[3][32 * 136];

    const int tid  = threadIdx.x;
    const int warp = tid >> 5;
    const int lane = tid & 31;
    const int G = lane >> 2, T = lane & 3;
    const int wm = (warp & 3) * 32;
    const int wn = (warp >> 2) * 64;
    const int row0 = blockIdx.y * 128;
    const int col0 = blockIdx.x * 128;

    const int ar = tid >> 1;
    const int ac = (tid & 1) * 16;
    const int wr = tid >> 3;
    const int wc = (tid & 7) * 16;

    auto load_stage = [&](int st, int k0) {
        const __half* ap = A + (size_t)(row0 + ar) * K + k0 + ac;
        cp16(&As[st][ar * 40 + ac],     ap);
        cp16(&As[st][ar * 40 + ac + 8], ap + 8);
        const __half* wp = W + (size_t)(k0 + wr) * N + col0 + wc;
        cp16(&Ws[st][wr * 136 + wc],     wp);
        cp16(&Ws[st][wr * 136 + wc + 8], wp + 8);
    };

    float acc[2][8][4] = {};
    const int NK = K >> 5;

    load_stage(0, 0);  cp_commit();
    load_stage(1, 32); cp_commit();

    for (int i = 0; i < NK; i++) {
        cp_wait<1>();
        __syncthreads();
        if (i + 2 < NK) load_stage((i + 2) % 3, (i + 2) << 5);
        cp_commit();
        const int st = i % 3;

        #pragma unroll
        for (int kc = 0; kc < 2; kc++) {
            uint32_t af[2][4];
            #pragma unroll
            for (int mt = 0; mt < 2; mt++)
                ldsm4(af[mt][0], af[mt][1], af[mt][2], af[mt][3],
                      &As[st][(wm + mt * 16 + (lane & 15)) * 40 + kc * 16 + (lane >> 4) * 8]);
            #pragma unroll
            for (int np = 0; np < 4; np++) {
                uint32_t b0, b1, b2, b3;
                ldsm4t(b0, b1, b2, b3,
                       &Ws[st][(kc * 16 + (lane & 15)) * 136 + wn + np * 16 + (lane >> 4) * 8]);
                #pragma unroll
                for (int mt = 0; mt < 2; mt++) {
                    mma16816(acc[mt][np * 2],     af[mt][0], af[mt][1], af[mt][2], af[mt][3], b0, b1);
                    mma16816(acc[mt][np * 2 + 1], af[mt][0], af[mt][1], af[mt][2], af[mt][3], b2, b3);
                }
            }
        }
    }

    #pragma unroll
    for (int mt = 0; mt < 2; mt++) {
        int r = row0 + wm + mt * 16 + G;
        #pragma unroll
        for (int nt = 0; nt < 8; nt++) {
            int c = col0 + wn + nt * 8 + 2 * T;
            float2 bv = *(const float2*)(bias + c);
            float v00 = acc[mt][nt][0] + bv.x, v01 = acc[mt][nt][1] + bv.y;
            float v10 = acc[mt][nt][2] + bv.x, v11 = acc[mt][nt][3] + bv.y;
            if (OUT_HALF) {
                __half* C = (__half*)Cv;
                *(uint32_t*)(C + (size_t)r * N + c)       = packh2(v00, v01);
                *(uint32_t*)(C + (size_t)(r + 8) * N + c) = packh2(v10, v11);
            } else {
                float* C = (float*)Cv;
                float2 a0 = {v00, v01}, a1 = {v10, v11};
                *(float2*)(C + (size_t)r * N + c)       = a0;
                *(float2*)(C + (size_t)(r + 8) * N + c) = a1;
            }
        }
    }
}

// ---------------------------------------------------------------------------
// K/V projection via split-fp16 (unchanged from R12)
// ---------------------------------------------------------------------------
__global__ __launch_bounds__(256) void kv_proj(
    const __half* __restrict__ Ah, const __half* __restrict__ Al,
    const __half* __restrict__ Wkh, const __half* __restrict__ Wkl,
    const float* __restrict__ bk, __half* __restrict__ Kh,
    const __half* __restrict__ Wvh, const __half* __restrict__ Wvl,
    const float* __restrict__ bv, __half* __restrict__ Vh)
{
    __shared__ __half Ahs[2][64 * 40];
    __shared__ __half Als[2][64 * 40];
    __shared__ __half Whs[2][32 * 72];
    __shared__ __half Wls[2][32 * 72];

    const __half* Wh; const __half* Wl; const float* bias; __half* C;
    if (blockIdx.x == 0) { Wh = Wkh; Wl = Wkl; bias = bk; C = Kh; }
    else                 { Wh = Wvh; Wl = Wvl; bias = bv; C = Vh; }

    const int tid  = threadIdx.x;
    const int warp = tid >> 5;
    const int lane = tid & 31;
    const int G = lane >> 2, T = lane & 3;
    const int wm = (warp & 3) * 16;
    const int wn = (warp >> 2) * 32;
    const int row0 = blockIdx.y * 64;

    const int ar = tid >> 2;
    const int ac = (tid & 3) * 8;
    const int wr = tid >> 3;
    const int wc = (tid & 7) * 8;

    auto load_stage = [&](int st, int k0) {
        cp16(&Ahs[st][ar * 40 + ac], Ah + (size_t)(row0 + ar) * D_MODEL + k0 + ac);
        cp16(&Als[st][ar * 40 + ac], Al + (size_t)(row0 + ar) * D_MODEL + k0 + ac);
        cp16(&Whs[st][wr * 72 + wc], Wh + (size_t)(k0 + wr) * HDIM + wc);
        cp16(&Wls[st][wr * 72 + wc], Wl + (size_t)(k0 + wr) * HDIM + wc);
    };

    float acc[4][4] = {};
    const int NK = D_MODEL / 32;

    load_stage(0, 0); cp_commit();
    for (int i = 0; i < NK; i++) {
        int st = i & 1;
        if (i + 1 < NK) load_stage(st ^ 1, (i + 1) * 32);
        cp_commit();
        cp_wait<1>();
        __syncthreads();

        #pragma unroll
        for (int kc = 0; kc < 2; kc++) {
            uint32_t ah0, ah1, ah2, ah3, al0, al1, al2, al3;
            ldsm4(ah0, ah1, ah2, ah3,
                  &Ahs[st][(wm + (lane & 15)) * 40 + kc * 16 + (lane >> 4) * 8]);
            ldsm4(al0, al1, al2, al3,
                  &Als[st][(wm + (lane & 15)) * 40 + kc * 16 + (lane >> 4) * 8]);
            #pragma unroll
            for (int np = 0; np < 2; np++) {
                uint32_t bh0, bh1, bh2, bh3, bl0, bl1, bl2, bl3;
                ldsm4t(bh0, bh1, bh2, bh3,
                       &Whs[st][(kc * 16 + (lane & 15)) * 72 + wn + np * 16 + (lane >> 4) * 8]);
                ldsm4t(bl0, bl1, bl2, bl3,
                       &Wls[st][(kc * 16 + (lane & 15)) * 72 + wn + np * 16 + (lane >> 4) * 8]);
                mma16816(acc[np * 2],     ah0, ah1, ah2, ah3, bh0, bh1);
                mma16816(acc[np * 2 + 1], ah0, ah1, ah2, ah3, bh2, bh3);
                mma16816(acc[np * 2],     ah0, ah1, ah2, ah3, bl0, bl1);
                mma16816(acc[np * 2 + 1], ah0, ah1, ah2, ah3, bl2, bl3);
                mma16816(acc[np * 2],     al0, al1, al2, al3, bh0, bh1);
                mma16816(acc[np * 2 + 1], al0, al1, al2, al3, bh2, bh3);
            }
        }
        __syncthreads();
    }

    #pragma unroll
    for (int nt = 0; nt < 4; nt++) {
        int r = row0 + wm + G;
        int c = wn + nt * 8 + 2 * T;
        float2 bv2 = *(const float2*)(bias + c);
        *(uint32_t*)(C + (size_t)r * HDIM + c) =
            packh2(acc[nt][0] + bv2.x, acc[nt][1] + bv2.y);
        *(uint32_t*)(C + (size_t)(r + 8) * HDIM + c) =
            packh2(acc[nt][2] + bv2.x, acc[nt][3] + bv2.y);
    }
}

// ---------------------------------------------------------------------------
// fp16 FlashAttention (MQA). 4 warps x 32 q-rows (two 16-row sets A/B per
// warp): each K/V fragment ldsm is shared by both sets' MMAs. Per-row FP op
// sequence byte-identical to R12 (l is reduced ONCE, per tile — the R13 bug
// was a duplicate epilogue reduction). 3-stage cp.async ring, unconditional
// commits. grid (S/128, B*H), 128 threads.
// ---------------------------------------------------------------------------
#define SC 0.18033688011112042f   // 0.125 * log2(e)
#define STG 9216                  // halves per stage

__global__ __launch_bounds__(128, 2) void mqa_attn_h(
    const __half* __restrict__ gQ, const __half* __restrict__ gK,
    const __half* __restrict__ gV, __half* __restrict__ gatt)
{
    __shared__ __half SM[3 * STG];

    const int tid  = threadIdx.x;
    const int warp = tid >> 5;       // 0..3
    const int lane = tid & 31;
    const int G = lane >> 2, T = lane & 3;
    const int q0 = blockIdx.x * 128;
    const int b  = blockIdx.y >> 4;
    const int h  = blockIdx.y & 15;
    const int qb = warp * 32;        // 32 q-rows per warp (sets A/B)

    const __half* kbase = gK + (size_t)b * S_LEN * HDIM;
    const __half* vbase = gV + (size_t)b * S_LEN * HDIM;

    const int kr = tid >> 1;             // 0..63
    const int kc = (tid & 1) * 32;       // 0 or 32

    auto load_kv = [&](int st, int kt) {   // 8 cp16/thread; no commit inside
        __half* Kd = SM + st * STG;
        __half* Vd = Kd + 4608;
        const __half* kp = kbase + (size_t)(kt + kr) * HDIM + kc;
        const __half* vp = vbase + (size_t)(kt + kr) * HDIM + kc;
        cp16(&Kd[kr * 72 + kc],      kp);
        cp16(&Kd[kr * 72 + kc + 8],  kp + 8);
        cp16(&Kd[kr * 72 + kc + 16], kp + 16);
        cp16(&Kd[kr * 72 + kc + 24], kp + 24);
        cp16(&Vd[kr * 72 + kc],      vp);
        cp16(&Vd[kr * 72 + kc + 8],  vp + 8);
        cp16(&Vd[kr * 72 + kc + 16], vp + 16);
        cp16(&Vd[kr * 72 + kc + 24], vp + 24);
    };

    {
        const __half* qsrc = gQ + ((size_t)(b * S_LEN + q0)) * D_MODEL + h * HDIM;
        #pragma unroll
        for (int p = 0; p < 8; p++) {
            int idx = p * 128 + tid;
            int r = idx >> 3, c8 = (idx & 7) * 8;
            cp16(&SM[r * 72 + c8], qsrc + (size_t)r * D_MODEL + c8);
        }
        cp_commit();
    }
    load_kv(1, 0);  cp_commit();
    load_kv(2, 64); cp_commit();

    cp_wait<2>();            // Q group complete (this thread)
    __syncthreads();         // all threads' Q copies visible
    uint32_t qfa[4][4], qfb[4][4];
    #pragma unroll
    for (int kq = 0; kq < 4; kq++) {
        ldsm4(qfa[kq][0], qfa[kq][1], qfa[kq][2], qfa[kq][3],
              &SM[(qb + (lane & 15)) * 72 + kq * 16 + (lane >> 4) * 8]);
        ldsm4(qfb[kq][0], qfb[kq][1], qfb[kq][2], qfb[kq][3],
              &SM[(qb + 16 + (lane & 15)) * 72 + kq * 16 + (lane >> 4) * 8]);
    }

    float oa[8][4] = {}, ob[8][4] = {};
    float m0a = -INFINITY, m1a = -INFINITY, l0a = 0.f, l1a = 0.f;
    float m0b = -INFINITY, m1b = -INFINITY, l0b = 0.f, l1b = 0.f;

    const int NT = S_LEN / 64;
    for (int i = 0; i < NT; i++) {
        cp_wait<1>();
        __syncthreads();
        if (i + 2 < NT) load_kv(i % 3, (i + 2) * 64);
        cp_commit();
        const int st = (i + 1) % 3;
        const __half* Ks = SM + st * STG;
        const __half* Vs = Ks + 4608;

        // S = Q * K^T : each K fragment feeds BOTH 16-row sets
        float sa[8][4], sb[8][4];
        #pragma unroll
        for (int nt = 0; nt < 8; nt++) {
            sa[nt][0]=0.f; sa[nt][1]=0.f; sa[nt][2]=0.f; sa[nt][3]=0.f;
            sb[nt][0]=0.f; sb[nt][1]=0.f; sb[nt][2]=0.f; sb[nt][3]=0.f;
        }
        #pragma unroll
        for (int nt = 0; nt < 8; nt++) {
            uint32_t b0, b1, b2, b3, b4, b5, b6, b7;
            const __half* kp = &Ks[(nt * 8 + (lane & 7)) * 72 + ((lane >> 3) * 8)];
            ldsm4(b0, b1, b2, b3, kp);
            ldsm4(b4, b5, b6, b7, kp + 32);
            mma16816(sa[nt], qfa[0][0], qfa[0][1], qfa[0][2], qfa[0][3], b0, b1);
            mma16816(sa[nt], qfa[1][0], qfa[1][1], qfa[1][2], qfa[1][3], b2, b3);
            mma16816(sa[nt], qfa[2][0], qfa[2][1], qfa[2][2], qfa[2][3], b4, b5);
            mma16816(sa[nt], qfa[3][0], qfa[3][1], qfa[3][2], qfa[3][3], b6, b7);
            mma16816(sb[nt], qfb[0][0], qfb[0][1], qfb[0][2], qfb[0][3], b0, b1);
            mma16816(sb[nt], qfb[1][0], qfb[1][1], qfb[1][2], qfb[1][3], b2, b3);
            mma16816(sb[nt], qfb[2][0], qfb[2][1], qfb[2][2], qfb[2][3], b4, b5);
            mma16816(sb[nt], qfb[3][0], qfb[3][1], qfb[3][2], qfb[3][3], b6, b7);
        }

        // Online softmax, set A (op sequence identical to R12)
        {
            float mx0 = -INFINITY, mx1 = -INFINITY;
            #pragma unroll
            for (int nt = 0; nt < 8; nt++) {
                mx0 = fmaxf(mx0, fmaxf(sa[nt][0], sa[nt][1]));
                mx1 = fmaxf(mx1, fmaxf(sa[nt][2], sa[nt][3]));
            }
            mx0 = fmaxf(mx0, __shfl_xor_sync(0xffffffffu, mx0, 1));
            mx0 = fmaxf(mx0, __shfl_xor_sync(0xffffffffu, mx0, 2));
            mx1 = fmaxf(mx1, __shfl_xor_sync(0xffffffffu, mx1, 1));
            mx1 = fmaxf(mx1, __shfl_xor_sync(0xffffffffu, mx1, 2));

            float mn0 = fmaxf(m0a, mx0), mn1 = fmaxf(m1a, mx1);
            float r0 = 0.f, r1 = 0.f;
            #pragma unroll
            for (int nt = 0; nt < 8; nt++) {
                sa[nt][0] = ex2((sa[nt][0] - mn0) * SC);
                sa[nt][1] = ex2((sa[nt][1] - mn0) * SC);
                sa[nt][2] = ex2((sa[nt][2] - mn1) * SC);
                sa[nt][3] = ex2((sa[nt][3] - mn1) * SC);
                r0 += sa[nt][0] + sa[nt][1];
                r1 += sa[nt][2] + sa[nt][3];
            }
            r0 += __shfl_xor_sync(0xffffffffu, r0, 1);
            r0 += __shfl_xor_sync(0xffffffffu, r0, 2);
            r1 += __shfl_xor_sync(0xffffffffu, r1, 1);
            r1 += __shfl_xor_sync(0xffffffffu, r1, 2);

            if (mn0 > m0a || mn1 > m1a) {
                float f0 = ex2((m0a - mn0) * SC);
                float f1 = ex2((m1a - mn1) * SC);
                l0a *= f0; l1a *= f1;
                #pragma unroll
                for (int ht = 0; ht < 8; ht++) {
                    oa[ht][0] *= f0; oa[ht][1] *= f0;
                    oa[ht][2] *= f1; oa[ht][3] *= f1;
                }
            }
            l0a += r0; l1a += r1;
            m0a = mn0; m1a = mn1;
        }

        // Online softmax, set B (identical sequence on its own state)
        {
            float mx0 = -INFINITY, mx1 = -INFINITY;
            #pragma unroll
            for (int nt = 0; nt < 8; nt++) {
                mx0 = fmaxf(mx0, fmaxf(sb[nt][0], sb[nt][1]));
                mx1 = fmaxf(mx1, fmaxf(sb[nt][2], sb[nt][3]));
            }
            mx0 = fmaxf(mx0, __shfl_xor_sync(0xffffffffu, mx0, 1));
            mx0 = fmaxf(mx0, __shfl_xor_sync(0xffffffffu, mx0, 2));
            mx1 = fmaxf(mx1, __shfl_xor_sync(0xffffffffu, mx1, 1));
            mx1 = fmaxf(mx1, __shfl_xor_sync(0xffffffffu, mx1, 2));

            float mn0 = fmaxf(m0b, mx0), mn1 = fmaxf(m1b, mx1);
            float r0 = 0.f, r1 = 0.f;
            #pragma unroll
            for (int nt = 0; nt < 8; nt++) {
                sb[nt][0] = ex2((sb[nt][0] - mn0) * SC);
                sb[nt][1] = ex2((sb[nt][1] - mn0) * SC);
                sb[nt][2] = ex2((sb[nt][2] - mn1) * SC);
                sb[nt][3] = ex2((sb[nt][3] - mn1) * SC);
                r0 += sb[nt][0] + sb[nt][1];
                r1 += sb[nt][2] + sb[nt][3];
            }
            r0 += __shfl_xor_sync(0xffffffffu, r0, 1);
            r0 += __shfl_xor_sync(0xffffffffu, r0, 2);
            r1 += __shfl_xor_sync(0xffffffffu, r1, 1);
            r1 += __shfl_xor_sync(0xffffffffu, r1, 2);

            if (mn0 > m0b || mn1 > m1b) {
                float f0 = ex2((m0b - mn0) * SC);
                float f1 = ex2((m1b - mn1) * SC);
                l0b *= f0; l1b *= f1;
                #pragma unroll
                for (int ht = 0; ht < 8; ht++) {
                    ob[ht][0] *= f0; ob[ht][1] *= f0;
                    ob[ht][2] *= f1; ob[ht][3] *= f1;
                }
            }
            l0b += r0; l1b += r1;
            m0b = mn0; m1b = mn1;
        }

        // O += P * V : each V fragment feeds BOTH sets
        #pragma unroll
        for (int ks = 0; ks < 4; ks++) {
            uint32_t a0 = packh2(sa[2*ks][0],   sa[2*ks][1]);
            uint32_t a1 = packh2(sa[2*ks][2],   sa[2*ks][3]);
            uint32_t a2 = packh2(sa[2*ks+1][0], sa[2*ks+1][1]);
            uint32_t a3 = packh2(sa[2*ks+1][2], sa[2*ks+1][3]);
            uint32_t c0 = packh2(sb[2*ks][0],   sb[2*ks][1]);
            uint32_t c1 = packh2(sb[2*ks][2],   sb[2*ks][3]);
            uint32_t c2 = packh2(sb[2*ks+1][0], sb[2*ks+1][1]);
            uint32_t c3 = packh2(sb[2*ks+1][2], sb[2*ks+1][3]);
            #pragma unroll
            for (int hp = 0; hp < 4; hp++) {
                uint32_t b0, b1, b2, b3;
                ldsm4t(b0, b1, b2, b3,
                       &Vs[(ks * 16 + (lane & 15)) * 72 + hp * 16 + (lane >> 4) * 8]);
                mma16816(oa[hp * 2],     a0, a1, a2, a3, b0, b1);
                mma16816(oa[hp * 2 + 1], a0, a1, a2, a3, b2, b3);
                mma16816(ob[hp * 2],     c0, c1, c2, c3, b0, b1);
                mma16816(ob[hp * 2 + 1], c0, c1, c2, c3, b2, b3);
            }
        }
    }

    // Epilogue: normalize, write half. l was already quad-reduced per tile —
    // use directly (R13's duplicate epilogue reduction was the 1/4-scale bug).
    {
        float i0 = 1.f / l0a, i1 = 1.f / l1a;
        __half* od  = gatt + ((size_t)(b * S_LEN + q0 + qb + G)) * D_MODEL + h * HDIM;
        __half* od8 = od + (size_t)8 * D_MODEL;
        #pragma unroll
        for (int ht = 0; ht < 8; ht++) {
            int c = ht * 8 + 2 * T;
            *(uint32_t*)(od + c)  = packh2(oa[ht][0] * i0, oa[ht][1] * i0);
            *(uint32_t*)(od8 + c) = packh2(oa[ht][2] * i1, oa[ht][3] * i1);
        }
    }
    {
        float i0 = 1.f / l0b, i1 = 1.f / l1b;
        __half* od  = gatt + ((size_t)(b * S_LEN + q0 + qb + 16 + G)) * D_MODEL + h * HDIM;
        __half* od8 = od + (size_t)8 * D_MODEL;
        #pragma unroll
        for (int ht = 0; ht < 8; ht++) {
            int c = ht * 8 + 2 * T;
            *(uint32_t*)(od + c)  = packh2(ob[ht][0] * i0, ob[ht][1] * i0);
            *(uint32_t*)(od8 + c) = packh2(ob[ht][2] * i1, ob[ht][3] * i1);
        }
    }
}

// ---------------------------------------------------------------------------
extern "C" void kernel_launch(void* const* d_in, const int* in_sizes, int n_in,
                              void* d_out, int out_size)
{
    const float* x  = (const float*)d_in[0];
    const float* Wq = (const float*)d_in[1];
    const float* bq = (const float*)d_in[2];
    const float* Wk = (const float*)d_in[3];
    const float* bk = (const float*)d_in[4];
    const float* Wv = (const float*)d_in[5];
    const float* bv = (const float*)d_in[6];
    const float* Wo = (const float*)d_in[7];
    const float* bo = (const float*)d_in[8];
    float* out = (float*)d_out;

    __half *xh, *xl, *Wqh, *Woh, *Wkh, *Wkl, *Wvh, *Wvl, *Qh, *Kh, *Vh, *ah;
    cudaGetSymbolAddress((void**)&xh,  g_xh);
    cudaGetSymbolAddress((void**)&xl,  g_xl);
    cudaGetSymbolAddress((void**)&Wqh, g_Wqh);
    cudaGetSymbolAddress((void**)&Woh, g_Woh);
    cudaGetSymbolAddress((void**)&Wkh, g_Wkh);
    cudaGetSymbolAddress((void**)&Wkl, g_Wkl);
    cudaGetSymbolAddress((void**)&Wvh, g_Wvh);
    cudaGetSymbolAddress((void**)&Wvl, g_Wvl);
    cudaGetSymbolAddress((void**)&Qh,  g_Qh);
    cudaGetSymbolAddress((void**)&Kh,  g_Kh);
    cudaGetSymbolAddress((void**)&Vh,  g_Vh);
    cudaGetSymbolAddress((void**)&ah,  g_ah);

    // One fused convert launch (bit-identical outputs)
    conv_all<<<3136, 256>>>(x, xh, xl, Wq, Wqh, Wo, Woh,
                            Wk, Wkh, Wkl, Wv, Wvh, Wvl);

    // Q projection (fp16 tensor)
    gemm_h<true><<<dim3(D_MODEL / 128, M_TOT / 128), 256>>>(xh, Wqh, bq, Qh, M_TOT, D_MODEL, D_MODEL);

    // K/V projections (split-fp16 tensor, fp32 quality)
    kv_proj<<<dim3(2, M_TOT / 64), 256>>>(xh, xl, Wkh, Wkl, bk, Kh, Wvh, Wvl, bv, Vh);

    // Attention (4 warps x 32 q-rows, shared K/V fragments)
    mqa_attn_h<<<dim3(S_LEN / 128, BATCH * NHEADS), 128>>>(Qh, Kh, Vh, ah);

    // Output projection (half in, float out)
    gemm_h<false><<<dim3(D_MODEL / 128, M_TOT / 128), 256>>>(ah, Woh, bo, out, M_TOT, D_MODEL, D_MODEL);
}

// round 15
// speedup vs baseline: 1.0292x; 1.0292x over previous
#include <cuda_runtime.h>
#include <cuda_fp16.h>
#include <math.h>
#include <stdint.h>

#define D_MODEL 1024
#define S_LEN   2048
#define BATCH   2
#define NHEADS  16
#define HDIM    64
#define M_TOT   (BATCH * S_LEN)   // 4096

// Scratch (no cudaMalloc allowed)
__device__ __half g_xh [(size_t)M_TOT * D_MODEL];
__device__ __half g_xl [(size_t)M_TOT * D_MODEL];
__device__ __half g_Wqh[(size_t)D_MODEL * D_MODEL];
__device__ __half g_Woh[(size_t)D_MODEL * D_MODEL];
__device__ __half g_Wkh[(size_t)D_MODEL * HDIM];
__device__ __half g_Wkl[(size_t)D_MODEL * HDIM];
__device__ __half g_Wvh[(size_t)D_MODEL * HDIM];
__device__ __half g_Wvl[(size_t)D_MODEL * HDIM];
__device__ __half g_Qh [(size_t)M_TOT * D_MODEL];
__device__ __half g_Kh [(size_t)M_TOT * HDIM];
__device__ __half g_Vh [(size_t)M_TOT * HDIM];
__device__ __half g_ah [(size_t)M_TOT * D_MODEL];

// ---------------------------------------------------------------------------
// helpers
// ---------------------------------------------------------------------------
__device__ __forceinline__ uint32_t s2u(const void* p) {
    return (uint32_t)__cvta_generic_to_shared(p);
}
__device__ __forceinline__ void cp16(void* s, const void* g) {
    asm volatile("cp.async.cg.shared.global [%0],[%1],16;\n" :: "r"(s2u(s)), "l"(g));
}
__device__ __forceinline__ void cp_commit() {
    asm volatile("cp.async.commit_group;\n");
}
template<int N> __device__ __forceinline__ void cp_wait() {
    asm volatile("cp.async.wait_group %0;\n" :: "n"(N));
}
__device__ __forceinline__ void ldsm4(uint32_t& r0, uint32_t& r1, uint32_t& r2, uint32_t& r3,
                                      const __half* p) {
    asm volatile("ldmatrix.sync.aligned.m8n8.x4.shared.b16 {%0,%1,%2,%3},[%4];"
                 : "=r"(r0), "=r"(r1), "=r"(r2), "=r"(r3) : "r"(s2u(p)));
}
__device__ __forceinline__ void ldsm4t(uint32_t& r0, uint32_t& r1, uint32_t& r2, uint32_t& r3,
                                       const __half* p) {
    asm volatile("ldmatrix.sync.aligned.m8n8.x4.trans.shared.b16 {%0,%1,%2,%3},[%4];"
                 : "=r"(r0), "=r"(r1), "=r"(r2), "=r"(r3) : "r"(s2u(p)));
}
__device__ __forceinline__ void mma16816(float c[4],
    uint32_t a0, uint32_t a1, uint32_t a2, uint32_t a3, uint32_t b0, uint32_t b1) {
    asm volatile(
        "mma.sync.aligned.m16n8k16.row.col.f32.f16.f16.f32 "
        "{%0,%1,%2,%3},{%4,%5,%6,%7},{%8,%9},{%0,%1,%2,%3};"
        : "+f"(c[0]), "+f"(c[1]), "+f"(c[2]), "+f"(c[3])
        : "r"(a0), "r"(a1), "r"(a2), "r"(a3), "r"(b0), "r"(b1));
}
__device__ __forceinline__ uint32_t packh2(float lo, float hi) {
    __half2 h = __floats2half2_rn(lo, hi);
    return *(uint32_t*)&h;
}
__device__ __forceinline__ float ex2(float x) {
    float y; asm("ex2.approx.f32 %0,%1;" : "=f"(y) : "f"(x)); return y;
}

// ---------------------------------------------------------------------------
// Fused fp32 -> fp16 convert for ALL operands in ONE launch (bit-identical)
// ---------------------------------------------------------------------------
__global__ __launch_bounds__(256) void conv_all(
    const float* __restrict__ x,  __half* __restrict__ xh,  __half* __restrict__ xl,
    const float* __restrict__ Wq, __half* __restrict__ Wqh,
    const float* __restrict__ Wo, __half* __restrict__ Woh,
    const float* __restrict__ Wk, __half* __restrict__ Wkh, __half* __restrict__ Wkl,
    const float* __restrict__ Wv, __half* __restrict__ Wvh, __half* __restrict__ Wvl)
{
    int b = blockIdx.x;
    const float* src; __half* dh; __half* dl;
    if (b < 2048)      { src = x;  dh = xh;  dl = xl;  }
    else if (b < 2560) { src = Wq; dh = Wqh; dl = 0; b -= 2048; }
    else if (b < 3072) { src = Wo; dh = Woh; dl = 0; b -= 2560; }
    else if (b < 3104) { src = Wk; dh = Wkh; dl = Wkl; b -= 3072; }
    else               { src = Wv; dh = Wvh; dl = Wvl; b -= 3104; }

    int i = (b * 256 + threadIdx.x) * 8;
    float v[8];
    *(float4*)(v)     = *(const float4*)(src + i);
    *(float4*)(v + 4) = *(const float4*)(src + i + 4);
    __half h[8];
    #pragma unroll
    for (int j = 0; j < 8; j++) h[j] = __float2half_rn(v[j]);
    *(uint4*)(dh + i) = *(uint4*)h;
    if (dl) {
        __half l[8];
        #pragma unroll
        for (int j = 0; j < 8; j++)
            l[j] = __float2half_rn(v[j] - __half2float(h[j]));
        *(uint4*)(dl + i) = *(uint4*)l;
    }
}

// ---------------------------------------------------------------------------
// Q-projection body (byte-identical math to R12's gemm_h<true>, N=K=1024)
// ---------------------------------------------------------------------------
__device__ __forceinline__ void qproj_body(
    const __half* __restrict__ A, const __half* __restrict__ W,
    const float* __restrict__ bias, __half* __restrict__ C,
    int bx, int by, char* smraw)
{
    __half* As = (__half*)smraw;                        // [3][128*40]
    __half* Ws = (__half*)(smraw + 3 * 128 * 40 * 2);   // [3][32*136]
    const int ASZ = 128 * 40, WSZ = 32 * 136;

    const int tid  = threadIdx.x;
    const int warp = tid >> 5;
    const int lane = tid & 31;
    const int G = lane >> 2, T = lane & 3;
    const int wm = (warp & 3) * 32;
    const int wn = (warp >> 2) * 64;
    const int row0 = by * 128;
    const int col0 = bx * 128;

    const int ar = tid >> 1;
    const int ac = (tid & 1) * 16;
    const int wr = tid >> 3;
    const int wc = (tid & 7) * 16;

    auto load_stage = [&](int st, int k0) {
        const __half* ap = A + (size_t)(row0 + ar) * 1024 + k0 + ac;
        cp16(&As[st * ASZ + ar * 40 + ac],     ap);
        cp16(&As[st * ASZ + ar * 40 + ac + 8], ap + 8);
        const __half* wp = W + (size_t)(k0 + wr) * 1024 + col0 + wc;
        cp16(&Ws[st * WSZ + wr * 136 + wc],     wp);
        cp16(&Ws[st * WSZ + wr * 136 + wc + 8], wp + 8);
    };

    float acc[2][8][4] = {};
    const int NK = 1024 >> 5;

    load_stage(0, 0);  cp_commit();
    load_stage(1, 32); cp_commit();

    for (int i = 0; i < NK; i++) {
        cp_wait<1>();
        __syncthreads();
        if (i + 2 < NK) load_stage((i + 2) % 3, (i + 2) << 5);
        cp_commit();
        const int st = i % 3;

        #pragma unroll
        for (int kc = 0; kc < 2; kc++) {
            uint32_t af[2][4];
            #pragma unroll
            for (int mt = 0; mt < 2; mt++)
                ldsm4(af[mt][0], af[mt][1], af[mt][2], af[mt][3],
                      &As[st * ASZ + (wm + mt * 16 + (lane & 15)) * 40 + kc * 16 + (lane >> 4) * 8]);
            #pragma unroll
            for (int np = 0; np < 4; np++) {
                uint32_t b0, b1, b2, b3;
                ldsm4t(b0, b1, b2, b3,
                       &Ws[st * WSZ + (kc * 16 + (lane & 15)) * 136 + wn + np * 16 + (lane >> 4) * 8]);
                #pragma unroll
                for (int mt = 0; mt < 2; mt++) {
                    mma16816(acc[mt][np * 2],     af[mt][0], af[mt][1], af[mt][2], af[mt][3], b0, b1);
                    mma16816(acc[mt][np * 2 + 1], af[mt][0], af[mt][1], af[mt][2], af[mt][3], b2, b3);
                }
            }
        }
    }

    #pragma unroll
    for (int mt = 0; mt < 2; mt++) {
        int r = row0 + wm + mt * 16 + G;
        #pragma unroll
        for (int nt = 0; nt < 8; nt++) {
            int c = col0 + wn + nt * 8 + 2 * T;
            float2 bv = *(const float2*)(bias + c);
            float v00 = acc[mt][nt][0] + bv.x, v01 = acc[mt][nt][1] + bv.y;
            float v10 = acc[mt][nt][2] + bv.x, v11 = acc[mt][nt][3] + bv.y;
            *(uint32_t*)(C + (size_t)r * 1024 + c)       = packh2(v00, v01);
            *(uint32_t*)(C + (size_t)(r + 8) * 1024 + c) = packh2(v10, v11);
        }
    }
}

// ---------------------------------------------------------------------------
// K/V projection body (byte-identical math to R12's kv_proj)
// ---------------------------------------------------------------------------
__device__ __forceinline__ void kv_body(
    const __half* __restrict__ Ah, const __half* __restrict__ Al,
    const __half* __restrict__ Wh, const __half* __restrict__ Wl,
    const float* __restrict__ bias, __half* __restrict__ C,
    int by, char* smraw)
{
    __half* Ahs = (__half*)smraw;                  // [2][64*40]
    __half* Als = (__half*)(smraw + 10240);        // [2][64*40]
    __half* Whs = (__half*)(smraw + 20480);        // [2][32*72]
    __half* Wls = (__half*)(smraw + 29696);        // [2][32*72]
    const int AZ = 64 * 40, WZ = 32 * 72;

    const int tid  = threadIdx.x;
    const int warp = tid >> 5;
    const int lane = tid & 31;
    const int G = lane >> 2, T = lane & 3;
    const int wm = (warp & 3) * 16;
    const int wn = (warp >> 2) * 32;
    const int row0 = by * 64;

    const int ar = tid >> 2;
    const int ac = (tid & 3) * 8;
    const int wr = tid >> 3;
    const int wc = (tid & 7) * 8;

    auto load_stage = [&](int st, int k0) {
        cp16(&Ahs[st * AZ + ar * 40 + ac], Ah + (size_t)(row0 + ar) * D_MODEL + k0 + ac);
        cp16(&Als[st * AZ + ar * 40 + ac], Al + (size_t)(row0 + ar) * D_MODEL + k0 + ac);
        cp16(&Whs[st * WZ + wr * 72 + wc], Wh + (size_t)(k0 + wr) * HDIM + wc);
        cp16(&Wls[st * WZ + wr * 72 + wc], Wl + (size_t)(k0 + wr) * HDIM + wc);
    };

    float acc[4][4] = {};
    const int NK = D_MODEL / 32;

    load_stage(0, 0); cp_commit();
    for (int i = 0; i < NK; i++) {
        int st = i & 1;
        if (i + 1 < NK) load_stage(st ^ 1, (i + 1) * 32);
        cp_commit();
        cp_wait<1>();
        __syncthreads();

        #pragma unroll
        for (int kc = 0; kc < 2; kc++) {
            uint32_t ah0, ah1, ah2, ah3, al0, al1, al2, al3;
            ldsm4(ah0, ah1, ah2, ah3,
                  &Ahs[st * AZ + (wm + (lane & 15)) * 40 + kc * 16 + (lane >> 4) * 8]);
            ldsm4(al0, al1, al2, al3,
                  &Als[st * AZ + (wm + (lane & 15)) * 40 + kc * 16 + (lane >> 4) * 8]);
            #pragma unroll
            for (int np = 0; np < 2; np++) {
                uint32_t bh0, bh1, bh2, bh3, bl0, bl1, bl2, bl3;
                ldsm4t(bh0, bh1, bh2, bh3,
                       &Whs[st * WZ + (kc * 16 + (lane & 15)) * 72 + wn + np * 16 + (lane >> 4) * 8]);
                ldsm4t(bl0, bl1, bl2, bl3,
                       &Wls[st * WZ + (kc * 16 + (lane & 15)) * 72 + wn + np * 16 + (lane >> 4) * 8]);
                mma16816(acc[np * 2],     ah0, ah1, ah2, ah3, bh0, bh1);
                mma16816(acc[np * 2 + 1], ah0, ah1, ah2, ah3, bh2, bh3);
                mma16816(acc[np * 2],     ah0, ah1, ah2, ah3, bl0, bl1);
                mma16816(acc[np * 2 + 1], ah0, ah1, ah2, ah3, bl2, bl3);
                mma16816(acc[np * 2],     al0, al1, al2, al3, bh0, bh1);
                mma16816(acc[np * 2 + 1], al0, al1, al2, al3, bh2, bh3);
            }
        }
        __syncthreads();
    }

    #pragma unroll
    for (int nt = 0; nt < 4; nt++) {
        int r = row0 + wm + G;
        int c = wn + nt * 8 + 2 * T;
        float2 bv2 = *(const float2*)(bias + c);
        *(uint32_t*)(C + (size_t)r * HDIM + c) =
            packh2(acc[nt][0] + bv2.x, acc[nt][1] + bv2.y);
        *(uint32_t*)(C + (size_t)(r + 8) * HDIM + c) =
            packh2(acc[nt][2] + bv2.x, acc[nt][3] + bv2.y);
    }
}

// ---------------------------------------------------------------------------
// Fused projections: blocks [0,256) run Q-proj, [256,384) run K/V-proj.
// Bodies are byte-identical to their R12 kernels; smem is a byte union.
// ---------------------------------------------------------------------------
__global__ __launch_bounds__(256) void proj_fused(
    const __half* __restrict__ xh,  const __half* __restrict__ xl,
    const __half* __restrict__ Wqh, const float* __restrict__ bq, __half* __restrict__ Qh,
    const __half* __restrict__ Wkh, const __half* __restrict__ Wkl,
    const float* __restrict__ bk,  __half* __restrict__ Kh,
    const __half* __restrict__ Wvh, const __half* __restrict__ Wvl,
    const float* __restrict__ bv,  __half* __restrict__ Vh)
{
    __shared__ __align__(16) char smu[56832];
    int blk = blockIdx.x;
    if (blk < 256) {
        qproj_body(xh, Wqh, bq, Qh, blk & 7, blk >> 3, smu);
    } else {
        int idx = blk - 256;                 // 0..127
        if (idx < 64) kv_body(xh, xl, Wkh, Wkl, bk, Kh, idx, smu);
        else          kv_body(xh, xl, Wvh, Wvl, bv, Vh, idx - 64, smu);
    }
}

// ---------------------------------------------------------------------------
// O-projection GEMM (float out) — unchanged from R12
// ---------------------------------------------------------------------------
__global__ __launch_bounds__(256) void gemm_of(
    const __half* __restrict__ A, const __half* __restrict__ W,
    const float* __restrict__ bias, float* __restrict__ C)
{
    __shared__ __half As[3][128 * 40];
    __shared__ __half Ws[3][32 * 136];

    const int tid  = threadIdx.x;
    const int warp = tid >> 5;
    const int lane = tid & 31;
    const int G = lane >> 2, T = lane & 3;
    const int wm = (warp & 3) * 32;
    const int wn = (warp >> 2) * 64;
    const int row0 = blockIdx.y * 128;
    const int col0 = blockIdx.x * 128;

    const int ar = tid >> 1;
    const int ac = (tid & 1) * 16;
    const int wr = tid >> 3;
    const int wc = (tid & 7) * 16;

    auto load_stage = [&](int st, int k0) {
        const __half* ap = A + (size_t)(row0 + ar) * 1024 + k0 + ac;
        cp16(&As[st][ar * 40 + ac],     ap);
        cp16(&As[st][ar * 40 + ac + 8], ap + 8);
        const __half* wp = W + (size_t)(k0 + wr) * 1024 + col0 + wc;
        cp16(&Ws[st][wr * 136 + wc],     wp);
        cp16(&Ws[st][wr * 136 + wc + 8], wp + 8);
    };

    float acc[2][8][4] = {};
    const int NK = 1024 >> 5;

    load_stage(0, 0);  cp_commit();
    load_stage(1, 32); cp_commit();

    for (int i = 0; i < NK; i++) {
        cp_wait<1>();
        __syncthreads();
        if (i + 2 < NK) load_stage((i + 2) % 3, (i + 2) << 5);
        cp_commit();
        const int st = i % 3;

        #pragma unroll
        for (int kc = 0; kc < 2; kc++) {
            uint32_t af[2][4];
            #pragma unroll
            for (int mt = 0; mt < 2; mt++)
                ldsm4(af[mt][0], af[mt][1], af[mt][2], af[mt][3],
                      &As[st][(wm + mt * 16 + (lane & 15)) * 40 + kc * 16 + (lane >> 4) * 8]);
            #pragma unroll
            for (int np = 0; np < 4; np++) {
                uint32_t b0, b1, b2, b3;
                ldsm4t(b0, b1, b2, b3,
                       &Ws[st][(kc * 16 + (lane & 15)) * 136 + wn + np * 16 + (lane >> 4) * 8]);
                #pragma unroll
                for (int mt = 0; mt < 2; mt++) {
                    mma16816(acc[mt][np * 2],     af[mt][0], af[mt][1], af[mt][2], af[mt][3], b0, b1);
                    mma16816(acc[mt][np * 2 + 1], af[mt][0], af[mt][1], af[mt][2], af[mt][3], b2, b3);
                }
            }
        }
    }

    #pragma unroll
    for (int mt = 0; mt < 2; mt++) {
        int r = row0 + wm + mt * 16 + G;
        #pragma unroll
        for (int nt = 0; nt < 8; nt++) {
            int c = col0 + wn + nt * 8 + 2 * T;
            float2 bv = *(const float2*)(bias + c);
            float2 a0 = {acc[mt][nt][0] + bv.x, acc[mt][nt][1] + bv.y};
            float2 a1 = {acc[mt][nt][2] + bv.x, acc[mt][nt][3] + bv.y};
            *(float2*)(C + (size_t)r * 1024 + c)       = a0;
            *(float2*)(C + (size_t)(r + 8) * 1024 + c) = a1;
        }
    }
}

// ---------------------------------------------------------------------------
// fp16 FlashAttention (MQA) — EXACT R12 kernel (best measured: 150.8 us,
// frozen numerics). 8 warps x 16 q-rows, 3-stage ring, unconditional commits.
// ---------------------------------------------------------------------------
#define SC 0.18033688011112042f   // 0.125 * log2(e)
#define STG 9216                  // halves per stage

__global__ __launch_bounds__(256, 2) void mqa_attn_h(
    const __half* __restrict__ gQ, const __half* __restrict__ gK,
    const __half* __restrict__ gV, __half* __restrict__ gatt)
{
    __shared__ __half SM[3 * STG];

    const int tid  = threadIdx.x;
    const int warp = tid >> 5;
    const int lane = tid & 31;
    const int G = lane >> 2, T = lane & 3;
    const int q0 = blockIdx.x * 128;
    const int b  = blockIdx.y >> 4;
    const int h  = blockIdx.y & 15;
    const int qb = warp * 16;

    const __half* kbase = gK + (size_t)b * S_LEN * HDIM;
    const __half* vbase = gV + (size_t)b * S_LEN * HDIM;

    const int kr = tid >> 2;
    const int kc = (tid & 3) * 8;

    auto load_kv = [&](int st, int kt) {
        __half* Kd = SM + st * STG;
        __half* Vd = Kd + 4608;
        const __half* kp = kbase + (size_t)(kt + kr) * HDIM + kc;
        const __half* vp = vbase + (size_t)(kt + kr) * HDIM + kc;
        cp16(&Kd[kr * 72 + kc],      kp);
        cp16(&Kd[kr * 72 + kc + 32], kp + 32);
        cp16(&Vd[kr * 72 + kc],      vp);
        cp16(&Vd[kr * 72 + kc + 32], vp + 32);
    };

    {
        const __half* qsrc = gQ + ((size_t)(b * S_LEN + q0)) * D_MODEL + h * HDIM;
        #pragma unroll
        for (int p = 0; p < 4; p++) {
            int idx = p * 256 + tid;
            int r = idx >> 3, c8 = (idx & 7) * 8;
            cp16(&SM[r * 72 + c8], qsrc + (size_t)r * D_MODEL + c8);
        }
        cp_commit();
    }
    load_kv(1, 0);  cp_commit();
    load_kv(2, 64); cp_commit();

    cp_wait<2>();            // Q group complete (this thread)
    __syncthreads();         // all threads' Q copies visible
    uint32_t qf[4][4];
    #pragma unroll
    for (int kq = 0; kq < 4; kq++)
        ldsm4(qf[kq][0], qf[kq][1], qf[kq][2], qf[kq][3],
              &SM[(qb + (lane & 15)) * 72 + kq * 16 + (lane >> 4) * 8]);

    float o_acc[8][4] = {};
    float m0 = -INFINITY, m1 = -INFINITY, l0 = 0.f, l1 = 0.f;

    const int NT = S_LEN / 64;
    for (int i = 0; i < NT; i++) {
        cp_wait<1>();
        __syncthreads();
        if (i + 2 < NT) load_kv(i % 3, (i + 2) * 64);
        cp_commit();
        const int st = (i + 1) % 3;
        const __half* Ks = SM + st * STG;
        const __half* Vs = Ks + 4608;

        float s[8][4];
        #pragma unroll
        for (int nt = 0; nt < 8; nt++) { s[nt][0]=0.f; s[nt][1]=0.f; s[nt][2]=0.f; s[nt][3]=0.f; }
        #pragma unroll
        for (int nt = 0; nt < 8; nt++) {
            uint32_t b0, b1, b2, b3, b4, b5, b6, b7;
            const __half* kp = &Ks[(nt * 8 + (lane & 7)) * 72 + ((lane >> 3) * 8)];
            ldsm4(b0, b1, b2, b3, kp);
            ldsm4(b4, b5, b6, b7, kp + 32);
            mma16816(s[nt], qf[0][0], qf[0][1], qf[0][2], qf[0][3], b0, b1);
            mma16816(s[nt], qf[1][0], qf[1][1], qf[1][2], qf[1][3], b2, b3);
            mma16816(s[nt], qf[2][0], qf[2][1], qf[2][2], qf[2][3], b4, b5);
            mma16816(s[nt], qf[3][0], qf[3][1], qf[3][2], qf[3][3], b6, b7);
        }

        float mx0 = -INFINITY, mx1 = -INFINITY;
        #pragma unroll
        for (int nt = 0; nt < 8; nt++) {
            mx0 = fmaxf(mx0, fmaxf(s[nt][0], s[nt][1]));
            mx1 = fmaxf(mx1, fmaxf(s[nt][2], s[nt][3]));
        }
        mx0 = fmaxf(mx0, __shfl_xor_sync(0xffffffffu, mx0, 1));
        mx0 = fmaxf(mx0, __shfl_xor_sync(0xffffffffu, mx0, 2));
        mx1 = fmaxf(mx1, __shfl_xor_sync(0xffffffffu, mx1, 1));
        mx1 = fmaxf(mx1, __shfl_xor_sync(0xffffffffu, mx1, 2));

        float mn0 = fmaxf(m0, mx0), mn1 = fmaxf(m1, mx1);
        float r0 = 0.f, r1 = 0.f;
        #pragma unroll
        for (int nt = 0; nt < 8; nt++) {
            s[nt][0] = ex2((s[nt][0] - mn0) * SC);
            s[nt][1] = ex2((s[nt][1] - mn0) * SC);
            s[nt][2] = ex2((s[nt][2] - mn1) * SC);
            s[nt][3] = ex2((s[nt][3] - mn1) * SC);
            r0 += s[nt][0] + s[nt][1];
            r1 += s[nt][2] + s[nt][3];
        }
        r0 += __shfl_xor_sync(0xffffffffu, r0, 1);
        r0 += __shfl_xor_sync(0xffffffffu, r0, 2);
        r1 += __shfl_xor_sync(0xffffffffu, r1, 1);
        r1 += __shfl_xor_sync(0xffffffffu, r1, 2);

        if (mn0 > m0 || mn1 > m1) {
            float f0 = ex2((m0 - mn0) * SC);
            float f1 = ex2((m1 - mn1) * SC);
            l0 *= f0; l1 *= f1;
            #pragma unroll
            for (int ht = 0; ht < 8; ht++) {
                o_acc[ht][0] *= f0; o_acc[ht][1] *= f0;
                o_acc[ht][2] *= f1; o_acc[ht][3] *= f1;
            }
        }
        l0 += r0; l1 += r1;
        m0 = mn0; m1 = mn1;

        #pragma unroll
        for (int ks = 0; ks < 4; ks++) {
            uint32_t a0 = packh2(s[2*ks][0],   s[2*ks][1]);
            uint32_t a1 = packh2(s[2*ks][2],   s[2*ks][3]);
            uint32_t a2 = packh2(s[2*ks+1][0], s[2*ks+1][1]);
            uint32_t a3 = packh2(s[2*ks+1][2], s[2*ks+1][3]);
            #pragma unroll
            for (int hp = 0; hp < 4; hp++) {
                uint32_t b0, b1, b2, b3;
                ldsm4t(b0, b1, b2, b3,
                       &Vs[(ks * 16 + (lane & 15)) * 72 + hp * 16 + (lane >> 4) * 8]);
                mma16816(o_acc[hp * 2],     a0, a1, a2, a3, b0, b1);
                mma16816(o_acc[hp * 2 + 1], a0, a1, a2, a3, b2, b3);
            }
        }
    }

    float i0 = 1.f / l0, i1 = 1.f / l1;
    __half* od  = gatt + ((size_t)(b * S_LEN + q0 + qb + G)) * D_MODEL + h * HDIM;
    __half* od8 = od + (size_t)8 * D_MODEL;
    #pragma unroll
    for (int ht = 0; ht < 8; ht++) {
        int c = ht * 8 + 2 * T;
        *(uint32_t*)(od + c)  = packh2(o_acc[ht][0] * i0, o_acc[ht][1] * i0);
        *(uint32_t*)(od8 + c) = packh2(o_acc[ht][2] * i1, o_acc[ht][3] * i1);
    }
}

// ---------------------------------------------------------------------------
extern "C" void kernel_launch(void* const* d_in, const int* in_sizes, int n_in,
                              void* d_out, int out_size)
{
    const float* x  = (const float*)d_in[0];
    const float* Wq = (const float*)d_in[1];
    const float* bq = (const float*)d_in[2];
    const float* Wk = (const float*)d_in[3];
    const float* bk = (const float*)d_in[4];
    const float* Wv = (const float*)d_in[5];
    const float* bv = (const float*)d_in[6];
    const float* Wo = (const float*)d_in[7];
    const float* bo = (const float*)d_in[8];
    float* out = (float*)d_out;

    __half *xh, *xl, *Wqh, *Woh, *Wkh, *Wkl, *Wvh, *Wvl, *Qh, *Kh, *Vh, *ah;
    cudaGetSymbolAddress((void**)&xh,  g_xh);
    cudaGetSymbolAddress((void**)&xl,  g_xl);
    cudaGetSymbolAddress((void**)&Wqh, g_Wqh);
    cudaGetSymbolAddress((void**)&Woh, g_Woh);
    cudaGetSymbolAddress((void**)&Wkh, g_Wkh);
    cudaGetSymbolAddress((void**)&Wkl, g_Wkl);
    cudaGetSymbolAddress((void**)&Wvh, g_Wvh);
    cudaGetSymbolAddress((void**)&Wvl, g_Wvl);
    cudaGetSymbolAddress((void**)&Qh,  g_Qh);
    cudaGetSymbolAddress((void**)&Kh,  g_Kh);
    cudaGetSymbolAddress((void**)&Vh,  g_Vh);
    cudaGetSymbolAddress((void**)&ah,  g_ah);

    // One fused convert launch (bit-identical outputs)
    conv_all<<<3136, 256>>>(x, xh, xl, Wq, Wqh, Wo, Woh,
                            Wk, Wkh, Wkl, Wv, Wvh, Wvl);

    // Fused Q + K/V projections (independent; one launch fills the chip)
    proj_fused<<<384, 256>>>(xh, xl, Wqh, bq, Qh,
                             Wkh, Wkl, bk, Kh, Wvh, Wvl, bv, Vh);

    // Attention (exact R12 kernel)
    mqa_attn_h<<<dim3(S_LEN / 128, BATCH * NHEADS), 256>>>(Qh, Kh, Vh, ah);

    // Output projection (half in, float out)
    gemm_of<<<dim3(8, 32), 256>>>(ah, Woh, bo, out);
}

// round 16
// speedup vs baseline: 1.0390x; 1.0095x over previous
#include <cuda_runtime.h>
#include <cuda_fp16.h>
#include <math.h>
#include <stdint.h>

#define D_MODEL 1024
#define S_LEN   2048
#define BATCH   2
#define NHEADS  16
#define HDIM    64
#define M_TOT   (BATCH * S_LEN)   // 4096

// Scratch (no cudaMalloc allowed)
__device__ __half g_xh [(size_t)M_TOT * D_MODEL];
__device__ __half g_xl [(size_t)M_TOT * D_MODEL];
__device__ __half g_Wqh[(size_t)D_MODEL * D_MODEL];
__device__ __half g_Woh[(size_t)D_MODEL * D_MODEL];
__device__ __half g_Wkh[(size_t)D_MODEL * HDIM];
__device__ __half g_Wkl[(size_t)D_MODEL * HDIM];
__device__ __half g_Wvh[(size_t)D_MODEL * HDIM];
__device__ __half g_Wvl[(size_t)D_MODEL * HDIM];
__device__ __half g_Qh [(size_t)M_TOT * D_MODEL];
__device__ __half g_Kh [(size_t)M_TOT * HDIM];
__device__ __half g_Vh [(size_t)M_TOT * HDIM];
__device__ __half g_ah [(size_t)M_TOT * D_MODEL];

// ---------------------------------------------------------------------------
// helpers
// ---------------------------------------------------------------------------
__device__ __forceinline__ uint32_t s2u(const void* p) {
    return (uint32_t)__cvta_generic_to_shared(p);
}
__device__ __forceinline__ void cp16(void* s, const void* g) {
    asm volatile("cp.async.cg.shared.global [%0],[%1],16;\n" :: "r"(s2u(s)), "l"(g));
}
__device__ __forceinline__ void cp_commit() {
    asm volatile("cp.async.commit_group;\n");
}
template<int N> __device__ __forceinline__ void cp_wait() {
    asm volatile("cp.async.wait_group %0;\n" :: "n"(N));
}
__device__ __forceinline__ void ldsm4(uint32_t& r0, uint32_t& r1, uint32_t& r2, uint32_t& r3,
                                      const __half* p) {
    asm volatile("ldmatrix.sync.aligned.m8n8.x4.shared.b16 {%0,%1,%2,%3},[%4];"
                 : "=r"(r0), "=r"(r1), "=r"(r2), "=r"(r3) : "r"(s2u(p)));
}
__device__ __forceinline__ void ldsm4t(uint32_t& r0, uint32_t& r1, uint32_t& r2, uint32_t& r3,
                                       const __half* p) {
    asm volatile("ldmatrix.sync.aligned.m8n8.x4.trans.shared.b16 {%0,%1,%2,%3},[%4];"
                 : "=r"(r0), "=r"(r1), "=r"(r2), "=r"(r3) : "r"(s2u(p)));
}
__device__ __forceinline__ void mma16816(float c[4],
    uint32_t a0, uint32_t a1, uint32_t a2, uint32_t a3, uint32_t b0, uint32_t b1) {
    asm volatile(
        "mma.sync.aligned.m16n8k16.row.col.f32.f16.f16.f32 "
        "{%0,%1,%2,%3},{%4,%5,%6,%7},{%8,%9},{%0,%1,%2,%3};"
        : "+f"(c[0]), "+f"(c[1]), "+f"(c[2]), "+f"(c[3])
        : "r"(a0), "r"(a1), "r"(a2), "r"(a3), "r"(b0), "r"(b1));
}
__device__ __forceinline__ uint32_t packh2(float lo, float hi) {
    __half2 h = __floats2half2_rn(lo, hi);
    return *(uint32_t*)&h;
}
__device__ __forceinline__ float ex2(float x) {
    float y; asm("ex2.approx.f32 %0,%1;" : "=f"(y) : "f"(x)); return y;
}

// ---------------------------------------------------------------------------
// Fused fp32 -> fp16 convert for ALL operands in ONE launch (bit-identical)
// ---------------------------------------------------------------------------
__global__ __launch_bounds__(256) void conv_all(
    const float* __restrict__ x,  __half* __restrict__ xh,  __half* __restrict__ xl,
    const float* __restrict__ Wq, __half* __restrict__ Wqh,
    const float* __restrict__ Wo, __half* __restrict__ Woh,
    const float* __restrict__ Wk, __half* __restrict__ Wkh, __half* __restrict__ Wkl,
    const float* __restrict__ Wv, __half* __restrict__ Wvh, __half* __restrict__ Wvl)
{
    int b = blockIdx.x;
    const float* src; __half* dh; __half* dl;
    if (b < 2048)      { src = x;  dh = xh;  dl = xl;  }
    else if (b < 2560) { src = Wq; dh = Wqh; dl = 0; b -= 2048; }
    else if (b < 3072) { src = Wo; dh = Woh; dl = 0; b -= 2560; }
    else if (b < 3104) { src = Wk; dh = Wkh; dl = Wkl; b -= 3072; }
    else               { src = Wv; dh = Wvh; dl = Wvl; b -= 3104; }

    int i = (b * 256 + threadIdx.x) * 8;
    float v[8];
    *(float4*)(v)     = *(const float4*)(src + i);
    *(float4*)(v + 4) = *(const float4*)(src + i + 4);
    __half h[8];
    #pragma unroll
    for (int j = 0; j < 8; j++) h[j] = __float2half_rn(v[j]);
    *(uint4*)(dh + i) = *(uint4*)h;
    if (dl) {
        __half l[8];
        #pragma unroll
        for (int j = 0; j < 8; j++)
            l[j] = __float2half_rn(v[j] - __half2float(h[j]));
        *(uint4*)(dl + i) = *(uint4*)l;
    }
}

// ---------------------------------------------------------------------------
// 128x128 GEMM body, 4-stage cp.async ring (prefetch distance 3).
// MMA k-order per thread identical to the 3-stage version -> bit-identical.
// OUT_HALF: half output (Q proj); else float (O proj).
// smem: As 4*[128*40], Ws 4*[32*136] = 75776 bytes.
// ---------------------------------------------------------------------------
#define GQ_SMEM 75776

template<bool OUT_HALF>
__device__ __forceinline__ void gemm128_body(
    const __half* __restrict__ A, const __half* __restrict__ W,
    const float* __restrict__ bias, void* __restrict__ Cv,
    int bx, int by, char* smraw)
{
    __half* As = (__half*)smraw;                        // [4][128*40]
    __half* Ws = (__half*)(smraw + 4 * 128 * 40 * 2);   // [4][32*136]
    const int ASZ = 128 * 40, WSZ = 32 * 136;

    const int tid  = threadIdx.x;
    const int warp = tid >> 5;
    const int lane = tid & 31;
    const int G = lane >> 2, T = lane & 3;
    const int wm = (warp & 3) * 32;
    const int wn = (warp >> 2) * 64;
    const int row0 = by * 128;
    const int col0 = bx * 128;

    const int ar = tid >> 1;
    const int ac = (tid & 1) * 16;
    const int wr = tid >> 3;
    const int wc = (tid & 7) * 16;

    auto load_stage = [&](int st, int k0) {
        const __half* ap = A + (size_t)(row0 + ar) * 1024 + k0 + ac;
        cp16(&As[st * ASZ + ar * 40 + ac],     ap);
        cp16(&As[st * ASZ + ar * 40 + ac + 8], ap + 8);
        const __half* wp = W + (size_t)(k0 + wr) * 1024 + col0 + wc;
        cp16(&Ws[st * WSZ + wr * 136 + wc],     wp);
        cp16(&Ws[st * WSZ + wr * 136 + wc + 8], wp + 8);
    };

    float acc[2][8][4] = {};
    const int NK = 1024 >> 5;   // 32

    load_stage(0, 0);  cp_commit();
    load_stage(1, 32); cp_commit();
    load_stage(2, 64); cp_commit();

    for (int i = 0; i < NK; i++) {
        cp_wait<2>();            // tile i complete (2 newest may be pending)
        __syncthreads();
        if (i + 3 < NK) load_stage((i + 3) & 3, (i + 3) << 5);
        cp_commit();             // unconditional: keeps group count honest
        const int st = i & 3;

        #pragma unroll
        for (int kc = 0; kc < 2; kc++) {
            uint32_t af[2][4];
            #pragma unroll
            for (int mt = 0; mt < 2; mt++)
                ldsm4(af[mt][0], af[mt][1], af[mt][2], af[mt][3],
                      &As[st * ASZ + (wm + mt * 16 + (lane & 15)) * 40 + kc * 16 + (lane >> 4) * 8]);
            #pragma unroll
            for (int np = 0; np < 4; np++) {
                uint32_t b0, b1, b2, b3;
                ldsm4t(b0, b1, b2, b3,
                       &Ws[st * WSZ + (kc * 16 + (lane & 15)) * 136 + wn + np * 16 + (lane >> 4) * 8]);
                #pragma unroll
                for (int mt = 0; mt < 2; mt++) {
                    mma16816(acc[mt][np * 2],     af[mt][0], af[mt][1], af[mt][2], af[mt][3], b0, b1);
                    mma16816(acc[mt][np * 2 + 1], af[mt][0], af[mt][1], af[mt][2], af[mt][3], b2, b3);
                }
            }
        }
    }

    #pragma unroll
    for (int mt = 0; mt < 2; mt++) {
        int r = row0 + wm + mt * 16 + G;
        #pragma unroll
        for (int nt = 0; nt < 8; nt++) {
            int c = col0 + wn + nt * 8 + 2 * T;
            float2 bv = *(const float2*)(bias + c);
            float v00 = acc[mt][nt][0] + bv.x, v01 = acc[mt][nt][1] + bv.y;
            float v10 = acc[mt][nt][2] + bv.x, v11 = acc[mt][nt][3] + bv.y;
            if (OUT_HALF) {
                __half* C = (__half*)Cv;
                *(uint32_t*)(C + (size_t)r * 1024 + c)       = packh2(v00, v01);
                *(uint32_t*)(C + (size_t)(r + 8) * 1024 + c) = packh2(v10, v11);
            } else {
                float* C = (float*)Cv;
                float2 a0 = {v00, v01}, a1 = {v10, v11};
                *(float2*)(C + (size_t)r * 1024 + c)       = a0;
                *(float2*)(C + (size_t)(r + 8) * 1024 + c) = a1;
            }
        }
    }
}

// ---------------------------------------------------------------------------
// K/V projection body (byte-identical math to R12's kv_proj, 2-stage)
// ---------------------------------------------------------------------------
__device__ __forceinline__ void kv_body(
    const __half* __restrict__ Ah, const __half* __restrict__ Al,
    const __half* __restrict__ Wh, const __half* __restrict__ Wl,
    const float* __restrict__ bias, __half* __restrict__ C,
    int by, char* smraw)
{
    __half* Ahs = (__half*)smraw;                  // [2][64*40]
    __half* Als = (__half*)(smraw + 10240);        // [2][64*40]
    __half* Whs = (__half*)(smraw + 20480);        // [2][32*72]
    __half* Wls = (__half*)(smraw + 29696);        // [2][32*72]
    const int AZ = 64 * 40, WZ = 32 * 72;

    const int tid  = threadIdx.x;
    const int warp = tid >> 5;
    const int lane = tid & 31;
    const int G = lane >> 2, T = lane & 3;
    const int wm = (warp & 3) * 16;
    const int wn = (warp >> 2) * 32;
    const int row0 = by * 64;

    const int ar = tid >> 2;
    const int ac = (tid & 3) * 8;
    const int wr = tid >> 3;
    const int wc = (tid & 7) * 8;

    auto load_stage = [&](int st, int k0) {
        cp16(&Ahs[st * AZ + ar * 40 + ac], Ah + (size_t)(row0 + ar) * D_MODEL + k0 + ac);
        cp16(&Als[st * AZ + ar * 40 + ac], Al + (size_t)(row0 + ar) * D_MODEL + k0 + ac);
        cp16(&Whs[st * WZ + wr * 72 + wc], Wh + (size_t)(k0 + wr) * HDIM + wc);
        cp16(&Wls[st * WZ + wr * 72 + wc], Wl + (size_t)(k0 + wr) * HDIM + wc);
    };

    float acc[4][4] = {};
    const int NK = D_MODEL / 32;

    load_stage(0, 0); cp_commit();
    for (int i = 0; i < NK; i++) {
        int st = i & 1;
        if (i + 1 < NK) load_stage(st ^ 1, (i + 1) * 32);
        cp_commit();
        cp_wait<1>();
        __syncthreads();

        #pragma unroll
        for (int kc = 0; kc < 2; kc++) {
            uint32_t ah0, ah1, ah2, ah3, al0, al1, al2, al3;
            ldsm4(ah0, ah1, ah2, ah3,
                  &Ahs[st * AZ + (wm + (lane & 15)) * 40 + kc * 16 + (lane >> 4) * 8]);
            ldsm4(al0, al1, al2, al3,
                  &Als[st * AZ + (wm + (lane & 15)) * 40 + kc * 16 + (lane >> 4) * 8]);
            #pragma unroll
            for (int np = 0; np < 2; np++) {
                uint32_t bh0, bh1, bh2, bh3, bl0, bl1, bl2, bl3;
                ldsm4t(bh0, bh1, bh2, bh3,
                       &Whs[st * WZ + (kc * 16 + (lane & 15)) * 72 + wn + np * 16 + (lane >> 4) * 8]);
                ldsm4t(bl0, bl1, bl2, bl3,
                       &Wls[st * WZ + (kc * 16 + (lane & 15)) * 72 + wn + np * 16 + (lane >> 4) * 8]);
                mma16816(acc[np * 2],     ah0, ah1, ah2, ah3, bh0, bh1);
                mma16816(acc[np * 2 + 1], ah0, ah1, ah2, ah3, bh2, bh3);
                mma16816(acc[np * 2],     ah0, ah1, ah2, ah3, bl0, bl1);
                mma16816(acc[np * 2 + 1], ah0, ah1, ah2, ah3, bl2, bl3);
                mma16816(acc[np * 2],     al0, al1, al2, al3, bh0, bh1);
                mma16816(acc[np * 2 + 1], al0, al1, al2, al3, bh2, bh3);
            }
        }
        __syncthreads();
    }

    #pragma unroll
    for (int nt = 0; nt < 4; nt++) {
        int r = row0 + wm + G;
        int c = wn + nt * 8 + 2 * T;
        float2 bv2 = *(const float2*)(bias + c);
        *(uint32_t*)(C + (size_t)r * HDIM + c) =
            packh2(acc[nt][0] + bv2.x, acc[nt][1] + bv2.y);
        *(uint32_t*)(C + (size_t)(r + 8) * HDIM + c) =
            packh2(acc[nt][2] + bv2.x, acc[nt][3] + bv2.y);
    }
}

// ---------------------------------------------------------------------------
// Fused projections: blocks [0,256) Q-proj (4-stage), [256,384) K/V-proj.
// ---------------------------------------------------------------------------
__global__ __launch_bounds__(256) void proj_fused(
    const __half* __restrict__ xh,  const __half* __restrict__ xl,
    const __half* __restrict__ Wqh, const float* __restrict__ bq, __half* __restrict__ Qh,
    const __half* __restrict__ Wkh, const __half* __restrict__ Wkl,
    const float* __restrict__ bk,  __half* __restrict__ Kh,
    const __half* __restrict__ Wvh, const __half* __restrict__ Wvl,
    const float* __restrict__ bv,  __half* __restrict__ Vh)
{
    __shared__ __align__(16) char smu[GQ_SMEM];
    int blk = blockIdx.x;
    if (blk < 256) {
        gemm128_body<true>(xh, Wqh, bq, Qh, blk & 7, blk >> 3, smu);
    } else {
        int idx = blk - 256;                 // 0..127
        if (idx < 64) kv_body(xh, xl, Wkh, Wkl, bk, Kh, idx, smu);
        else          kv_body(xh, xl, Wvh, Wvl, bv, Vh, idx - 64, smu);
    }
}

// ---------------------------------------------------------------------------
// O-projection GEMM (float out), 4-stage
// ---------------------------------------------------------------------------
__global__ __launch_bounds__(256) void gemm_of(
    const __half* __restrict__ A, const __half* __restrict__ W,
    const float* __restrict__ bias, float* __restrict__ C)
{
    __shared__ __align__(16) char smu[GQ_SMEM];
    gemm128_body<false>(A, W, bias, C, blockIdx.x, blockIdx.y, smu);
}

// ---------------------------------------------------------------------------
// fp16 FlashAttention (MQA) — EXACT R12 kernel (best measured: 150.8 us,
// frozen numerics). 8 warps x 16 q-rows, 3-stage ring, unconditional commits.
// ---------------------------------------------------------------------------
#define SC 0.18033688011112042f   // 0.125 * log2(e)
#define STG 9216                  // halves per stage

__global__ __launch_bounds__(256, 2) void mqa_attn_h(
    const __half* __restrict__ gQ, const __half* __restrict__ gK,
    const __half* __restrict__ gV, __half* __restrict__ gatt)
{
    __shared__ __half SM[3 * STG];

    const int tid  = threadIdx.x;
    const int warp = tid >> 5;
    const int lane = tid & 31;
    const int G = lane >> 2, T = lane & 3;
    const int q0 = blockIdx.x * 128;
    const int b  = blockIdx.y >> 4;
    const int h  = blockIdx.y & 15;
    const int qb = warp * 16;

    const __half* kbase = gK + (size_t)b * S_LEN * HDIM;
    const __half* vbase = gV + (size_t)b * S_LEN * HDIM;

    const int kr = tid >> 2;
    const int kc = (tid & 3) * 8;

    auto load_kv = [&](int st, int kt) {
        __half* Kd = SM + st * STG;
        __half* Vd = Kd + 4608;
        const __half* kp = kbase + (size_t)(kt + kr) * HDIM + kc;
        const __half* vp = vbase + (size_t)(kt + kr) * HDIM + kc;
        cp16(&Kd[kr * 72 + kc],      kp);
        cp16(&Kd[kr * 72 + kc + 32], kp + 32);
        cp16(&Vd[kr * 72 + kc],      vp);
        cp16(&Vd[kr * 72 + kc + 32], vp + 32);
    };

    {
        const __half* qsrc = gQ + ((size_t)(b * S_LEN + q0)) * D_MODEL + h * HDIM;
        #pragma unroll
        for (int p = 0; p < 4; p++) {
            int idx = p * 256 + tid;
            int r = idx >> 3, c8 = (idx & 7) * 8;
            cp16(&SM[r * 72 + c8], qsrc + (size_t)r * D_MODEL + c8);
        }
        cp_commit();
    }
    load_kv(1, 0);  cp_commit();
    load_kv(2, 64); cp_commit();

    cp_wait<2>();            // Q group complete (this thread)
    __syncthreads();         // all threads' Q copies visible
    uint32_t qf[4][4];
    #pragma unroll
    for (int kq = 0; kq < 4; kq++)
        ldsm4(qf[kq][0], qf[kq][1], qf[kq][2], qf[kq][3],
              &SM[(qb + (lane & 15)) * 72 + kq * 16 + (lane >> 4) * 8]);

    float o_acc[8][4] = {};
    float m0 = -INFINITY, m1 = -INFINITY, l0 = 0.f, l1 = 0.f;

    const int NT = S_LEN / 64;
    for (int i = 0; i < NT; i++) {
        cp_wait<1>();
        __syncthreads();
        if (i + 2 < NT) load_kv(i % 3, (i + 2) * 64);
        cp_commit();
        const int st = (i + 1) % 3;
        const __half* Ks = SM + st * STG;
        const __half* Vs = Ks + 4608;

        float s[8][4];
        #pragma unroll
        for (int nt = 0; nt < 8; nt++) { s[nt][0]=0.f; s[nt][1]=0.f; s[nt][2]=0.f; s[nt][3]=0.f; }
        #pragma unroll
        for (int nt = 0; nt < 8; nt++) {
            uint32_t b0, b1, b2, b3, b4, b5, b6, b7;
            const __half* kp = &Ks[(nt * 8 + (lane & 7)) * 72 + ((lane >> 3) * 8)];
            ldsm4(b0, b1, b2, b3, kp);
            ldsm4(b4, b5, b6, b7, kp + 32);
            mma16816(s[nt], qf[0][0], qf[0][1], qf[0][2], qf[0][3], b0, b1);
            mma16816(s[nt], qf[1][0], qf[1][1], qf[1][2], qf[1][3], b2, b3);
            mma16816(s[nt], qf[2][0], qf[2][1], qf[2][2], qf[2][3], b4, b5);
            mma16816(s[nt], qf[3][0], qf[3][1], qf[3][2], qf[3][3], b6, b7);
        }

        float mx0 = -INFINITY, mx1 = -INFINITY;
        #pragma unroll
        for (int nt = 0; nt < 8; nt++) {
            mx0 = fmaxf(mx0, fmaxf(s[nt][0], s[nt][1]));
            mx1 = fmaxf(mx1, fmaxf(s[nt][2], s[nt][3]));
        }
        mx0 = fmaxf(mx0, __shfl_xor_sync(0xffffffffu, mx0, 1));
        mx0 = fmaxf(mx0, __shfl_xor_sync(0xffffffffu, mx0, 2));
        mx1 = fmaxf(mx1, __shfl_xor_sync(0xffffffffu, mx1, 1));
        mx1 = fmaxf(mx1, __shfl_xor_sync(0xffffffffu, mx1, 2));

        float mn0 = fmaxf(m0, mx0), mn1 = fmaxf(m1, mx1);
        float r0 = 0.f, r1 = 0.f;
        #pragma unroll
        for (int nt = 0; nt < 8; nt++) {
            s[nt][0] = ex2((s[nt][0] - mn0) * SC);
            s[nt][1] = ex2((s[nt][1] - mn0) * SC);
            s[nt][2] = ex2((s[nt][2] - mn1) * SC);
            s[nt][3] = ex2((s[nt][3] - mn1) * SC);
            r0 += s[nt][0] + s[nt][1];
            r1 += s[nt][2] + s[nt][3];
        }
        r0 += __shfl_xor_sync(0xffffffffu, r0, 1);
        r0 += __shfl_xor_sync(0xffffffffu, r0, 2);
        r1 += __shfl_xor_sync(0xffffffffu, r1, 1);
        r1 += __shfl_xor_sync(0xffffffffu, r1, 2);

        if (mn0 > m0 || mn1 > m1) {
            float f0 = ex2((m0 - mn0) * SC);
            float f1 = ex2((m1 - mn1) * SC);
            l0 *= f0; l1 *= f1;
            #pragma unroll
            for (int ht = 0; ht < 8; ht++) {
                o_acc[ht][0] *= f0; o_acc[ht][1] *= f0;
                o_acc[ht][2] *= f1; o_acc[ht][3] *= f1;
            }
        }
        l0 += r0; l1 += r1;
        m0 = mn0; m1 = mn1;

        #pragma unroll
        for (int ks = 0; ks < 4; ks++) {
            uint32_t a0 = packh2(s[2*ks][0],   s[2*ks][1]);
            uint32_t a1 = packh2(s[2*ks][2],   s[2*ks][3]);
            uint32_t a2 = packh2(s[2*ks+1][0], s[2*ks+1][1]);
            uint32_t a3 = packh2(s[2*ks+1][2], s[2*ks+1][3]);
            #pragma unroll
            for (int hp = 0; hp < 4; hp++) {
                uint32_t b0, b1, b2, b3;
                ldsm4t(b0, b1, b2, b3,
                       &Vs[(ks * 16 + (lane & 15)) * 72 + hp * 16 + (lane >> 4) * 8]);
                mma16816(o_acc[hp * 2],     a0, a1, a2, a3, b0, b1);
                mma16816(o_acc[hp * 2 + 1], a0, a1, a2, a3, b2, b3);
            }
        }
    }

    float i0 = 1.f / l0, i1 = 1.f / l1;
    __half* od  = gatt + ((size_t)(b * S_LEN + q0 + qb + G)) * D_MODEL + h * HDIM;
    __half* od8 = od + (size_t)8 * D_MODEL;
    #pragma unroll
    for (int ht = 0; ht < 8; ht++) {
        int c = ht * 8 + 2 * T;
        *(uint32_t*)(od + c)  = packh2(o_acc[ht][0] * i0, o_acc[ht][1] * i0);
        *(uint32_t*)(od8 + c) = packh2(o_acc[ht][2] * i1, o_acc[ht][3] * i1);
    }
}

// ---------------------------------------------------------------------------
extern "C" void kernel_launch(void* const* d_in, const int* in_sizes, int n_in,
                              void* d_out, int out_size)
{
    const float* x  = (const float*)d_in[0];
    const float* Wq = (const float*)d_in[1];
    const float* bq = (const float*)d_in[2];
    const float* Wk = (const float*)d_in[3];
    const float* bk = (const float*)d_in[4];
    const float* Wv = (const float*)d_in[5];
    const float* bv = (const float*)d_in[6];
    const float* Wo = (const float*)d_in[7];
    const float* bo = (const float*)d_in[8];
    float* out = (float*)d_out;

    __half *xh, *xl, *Wqh, *Woh, *Wkh, *Wkl, *Wvh, *Wvl, *Qh, *Kh, *Vh, *ah;
    cudaGetSymbolAddress((void**)&xh,  g_xh);
    cudaGetSymbolAddress((void**)&xl,  g_xl);
    cudaGetSymbolAddress((void**)&Wqh, g_Wqh);
    cudaGetSymbolAddress((void**)&Woh, g_Woh);
    cudaGetSymbolAddress((void**)&Wkh, g_Wkh);
    cudaGetSymbolAddress((void**)&Wkl, g_Wkl);
    cudaGetSymbolAddress((void**)&Wvh, g_Wvh);
    cudaGetSymbolAddress((void**)&Wvl, g_Wvl);
    cudaGetSymbolAddress((void**)&Qh,  g_Qh);
    cudaGetSymbolAddress((void**)&Kh,  g_Kh);
    cudaGetSymbolAddress((void**)&Vh,  g_Vh);
    cudaGetSymbolAddress((void**)&ah,  g_ah);

    // One fused convert launch (bit-identical outputs)
    conv_all<<<3136, 256>>>(x, xh, xl, Wq, Wqh, Wo, Woh,
                            Wk, Wkh, Wkl, Wv, Wvh, Wvl);

    // Fused Q + K/V projections (Q path 4-stage pipelined)
    proj_fused<<<384, 256>>>(xh, xl, Wqh, bq, Qh,
                             Wkh, Wkl, bk, Kh, Wvh, Wvl, bv, Vh);

    // Attention (exact R12 kernel, frozen)
    mqa_attn_h<<<dim3(S_LEN / 128, BATCH * NHEADS), 256>>>(Qh, Kh, Vh, ah);

    // Output projection (half in, float out, 4-stage)
    gemm_of<<<dim3(8, 32), 256>>>(ah, Woh, bo, out);
}